// round 16
// baseline (speedup 1.0000x reference)
#include <cuda_runtime.h>
#include <cuda_bf16.h>

// Problem constants
#define B    32
#define LQ   32
#define DLEN 4096
#define P    16
#define D    2048
#define H    2048
#define V    50257
#define VPAD 50432            // 394 * 128

#define KSPLIT 32             // k-split for skinny GEMMs
#define TILE_N 64
#define KB     64

// ---------------- scratch (device globals; no allocation allowed) ----------------
__device__ float g_qrep[B * D];
__device__ float g_qenc[B * H];
__device__ float g_v[B * D];
__device__ float g_part[KSPLIT * B * 2048];      // GEMM partials (8 MB)
__device__ float g_c[B];
__device__ unsigned int g_mask[VPAD];            // per-id batch mask; self-cleaned
__device__ int   g_ids[VPAD];
__device__ unsigned int g_cmask[VPAD];
__device__ int   g_rank[V];
__device__ int   g_nids;
__device__ float g_y[(size_t)VPAD * B];          // dot table [slot][b] (6.5 MB)

// ---------------- mark: batch mask per used vocab id (also zeroes g_nids) ----------
__global__ void k_mark(const int* __restrict__ docs,
                       const int* __restrict__ plen) {
    int b = blockIdx.x;
    __shared__ int tot;
    if (threadIdx.x == 0) {
        int s = 0;
        #pragma unroll
        for (int q = 0; q < P; q++) s += plen[b * P + q];
        tot = s;
        if (b == 0) g_nids = 0;   // no reader until k_compact (next kernel)
    }
    __syncthreads();
    unsigned bit = 1u << b;
    for (int tt = threadIdx.x; tt < tot; tt += blockDim.x)
        atomicOr(&g_mask[docs[b * DLEN + tt]], bit);
}

// ---------------- compact used ids + masks; block-aggregated atomics ---------------
__global__ void k_compact() {
    __shared__ int warp_off[8];
    __shared__ int block_base;
    int i = blockIdx.x * 256 + threadIdx.x;
    unsigned m = (i < V) ? g_mask[i] : 0u;
    bool has = (m != 0u);
    if (has) g_mask[i] = 0u;                     // self-clean for next call
    unsigned ballot = __ballot_sync(0xFFFFFFFFu, has);
    int w = threadIdx.x >> 5, lane = threadIdx.x & 31;
    if (lane == 0) warp_off[w] = __popc(ballot);
    __syncthreads();
    if (threadIdx.x == 0) {
        int tot = 0;
        #pragma unroll
        for (int j = 0; j < 8; j++) { int c = warp_off[j]; warp_off[j] = tot; tot += c; }
        block_base = tot ? atomicAdd(&g_nids, tot) : 0;
    }
    __syncthreads();
    if (has) {
        int slot = block_base + warp_off[w] + __popc(ballot & ((1u << lane) - 1u));
        g_ids[slot] = i;
        g_cmask[slot] = m;
        g_rank[i] = slot;
    }
}

// ---------------- q_rep = masked mean; float4 + 2-way token MLP ----------------
__global__ void k_qrep(const int* __restrict__ queries,
                       const int* __restrict__ qlen,
                       const float* __restrict__ emb) {
    int b = blockIdx.x;
    __shared__ int toks[LQ];
    if (threadIdx.x < LQ) toks[threadIdx.x] = queries[b * LQ + threadIdx.x];
    int len = qlen[b];
    __syncthreads();
    int d4 = blockIdx.y * 256 + threadIdx.x;     // grid (B, 2) x 256 = 512 float4
    const float4* e4 = (const float4*)emb;
    float4 a0 = make_float4(0.f, 0.f, 0.f, 0.f);
    float4 a1 = make_float4(0.f, 0.f, 0.f, 0.f);
    int l = 0;
    for (; l + 2 <= len; l += 2) {
        float4 x = e4[(size_t)toks[l] * 512 + d4];
        float4 y = e4[(size_t)toks[l + 1] * 512 + d4];
        a0.x += x.x; a0.y += x.y; a0.z += x.z; a0.w += x.w;
        a1.x += y.x; a1.y += y.y; a1.z += y.z; a1.w += y.w;
    }
    if (l < len) {
        float4 x = e4[(size_t)toks[l] * 512 + d4];
        a0.x += x.x; a0.y += x.y; a0.z += x.z; a0.w += x.w;
    }
    float inv = 1.0f / (float)len;
    float4 r = make_float4((a0.x + a1.x) * inv, (a0.y + a1.y) * inv,
                           (a0.z + a1.z) * inv, (a0.w + a1.w) * inv);
    ((float4*)g_qrep)[(size_t)b * 512 + d4] = r;
}

// ---------------- skinny GEMM: broadcast LDS.128 A-quad inner loop -----------------
// As_t[k][row] (stride 36 floats, 16B-aligned): warp loads its 4-row quad as ONE
// broadcast LDS.128; Ws[n][k] scalar, conflict-free. 11 instr / 8 MACs.
__global__ void k_gemm(const float* __restrict__ A,
                       const float* __restrict__ W,
                       int transW) {
    const int n0 = blockIdx.x * TILE_N;
    const int k0 = blockIdx.y * KB;
    __shared__ __align__(16) float As_t[KB][36];   // [k][row], pad to 36
    __shared__ float Ws[TILE_N][KB + 1];

    const int t  = threadIdx.x;      // 256 threads
    const int tb = t >> 5;
    const int tn = t & 31;

    // A tile: flat = t + i*256; bb = flat&31 (consecutive banks per warp store),
    // kk = flat>>5. Global read is column-strided but A is tiny (L2-resident).
    #pragma unroll
    for (int i = 0; i < 8; i++) {
        int flat = t + i * 256;
        int bb = flat & 31, kk = flat >> 5;
        As_t[kk][bb] = A[bb * 2048 + k0 + kk];
    }
    // W tile: 1024 float4, 4 per thread (coalesced)
    if (!transW) {
        #pragma unroll
        for (int i = 0; i < 4; i++) {
            int f4 = t + i * 256;
            int nn = f4 >> 4, k4 = f4 & 15;
            float4 x = *(const float4*)(W + (size_t)(n0 + nn) * 2048 + k0 + k4 * 4);
            Ws[nn][k4 * 4 + 0] = x.x; Ws[nn][k4 * 4 + 1] = x.y;
            Ws[nn][k4 * 4 + 2] = x.z; Ws[nn][k4 * 4 + 3] = x.w;
        }
    } else {
        #pragma unroll
        for (int i = 0; i < 4; i++) {
            int f4 = t + i * 256;
            int kk = f4 >> 4, n4 = f4 & 15;
            float4 x = *(const float4*)(W + (size_t)(k0 + kk) * 2048 + n0 + n4 * 4);
            Ws[n4 * 4 + 0][kk] = x.x; Ws[n4 * 4 + 1][kk] = x.y;
            Ws[n4 * 4 + 2][kk] = x.z; Ws[n4 * 4 + 3][kk] = x.w;
        }
    }
    __syncthreads();

    float acc00 = 0.f, acc01 = 0.f, acc10 = 0.f, acc11 = 0.f;
    float acc20 = 0.f, acc21 = 0.f, acc30 = 0.f, acc31 = 0.f;
    #pragma unroll 16
    for (int k = 0; k < KB; k++) {
        float4 a = *(const float4*)&As_t[k][tb * 4];   // broadcast LDS.128
        float w0 = Ws[tn][k];
        float w1 = Ws[tn + 32][k];
        acc00 += a.x * w0; acc01 += a.x * w1;
        acc10 += a.y * w0; acc11 += a.y * w1;
        acc20 += a.z * w0; acc21 += a.z * w1;
        acc30 += a.w * w0; acc31 += a.w * w1;
    }

    float* out = g_part + (size_t)blockIdx.y * 32 * 2048;
    out[(tb * 4 + 0) * 2048 + n0 + tn]      = acc00;
    out[(tb * 4 + 0) * 2048 + n0 + tn + 32] = acc01;
    out[(tb * 4 + 1) * 2048 + n0 + tn]      = acc10;
    out[(tb * 4 + 1) * 2048 + n0 + tn + 32] = acc11;
    out[(tb * 4 + 2) * 2048 + n0 + tn]      = acc20;
    out[(tb * 4 + 2) * 2048 + n0 + tn + 32] = acc21;
    out[(tb * 4 + 3) * 2048 + n0 + tn]      = acc30;
    out[(tb * 4 + 3) * 2048 + n0 + tn + 32] = acc31;
}

// vectorized partial reduce over 16384 float4; 128 blocks x 128 threads
__global__ void k_reduce(float* __restrict__ C,
                         const float* __restrict__ bias,
                         int addBias) {
    int idx = blockIdx.x * 128 + threadIdx.x;
    const float4* part4 = (const float4*)g_part;
    float4 s = make_float4(0.f, 0.f, 0.f, 0.f);
    #pragma unroll
    for (int sp = 0; sp < KSPLIT; sp++) {
        float4 x = part4[sp * 16384 + idx];
        s.x += x.x; s.y += x.y; s.z += x.z; s.w += x.w;
    }
    if (addBias) {
        float4 bb = ((const float4*)bias)[idx & 511];
        s.x += bb.x; s.y += bb.y; s.z += bb.z; s.w += bb.w;
    }
    ((float4*)C)[idx] = s;
}

// c[b] = q_enc[b] . bias
__global__ void k_qc(const float* __restrict__ bias) {
    int b = blockIdx.x;
    float s = 0.0f;
    for (int i = threadIdx.x; i < H; i += 256) s += g_qenc[b * H + i] * bias[i];
    __shared__ float red[256];
    red[threadIdx.x] = s;
    __syncthreads();
    for (int o = 128; o; o >>= 1) {
        if (threadIdx.x < o) red[threadIdx.x] += red[threadIdx.x + o];
        __syncthreads();
    }
    if (threadIdx.x == 0) g_c[b] = red[0];
}

// ---------------- ydot: ONE WARP OWNS ONE FULL ROW --------------------------------
// Warp loads its entire 8KB emb row into registers (16 contiguous LDG.128/lane =
// one 64-line DRAM burst), then dots against each masked batch's v streamed from
// global (v = 256KB, L2/L1-resident). No smem staging, no z-chunking, no partials.
__global__ __launch_bounds__(256) void k_ydot(const float* __restrict__ emb) {
    const int t = threadIdx.x, w = t >> 5, lane = t & 31;
    const int row = blockIdx.x * 8 + w;
    if (row >= g_nids) return;

    const int id = g_ids[row];               // uniform per warp (broadcast load)
    unsigned mask = g_cmask[row];
    const float4* rp = (const float4*)(emb + (size_t)id * D);

    // full row into registers: 16 x LDG.128, contiguous 8KB
    float4 e[16];
    #pragma unroll
    for (int i = 0; i < 16; i++) e[i] = rp[lane + 32 * i];

    while (mask) {
        int b0 = __ffs(mask) - 1; mask &= mask - 1;
        int b1 = -1;
        if (mask) { b1 = __ffs(mask) - 1; mask &= mask - 1; }
        const float4* vp0 = (const float4*)(g_v + (size_t)b0 * D);
        const float4* vp1 = (b1 >= 0) ? (const float4*)(g_v + (size_t)b1 * D) : vp0;
        float s0 = 0.0f, s1 = 0.0f;
        #pragma unroll
        for (int i = 0; i < 16; i++) {
            float4 v0 = vp0[lane + 32 * i];
            float4 v1 = vp1[lane + 32 * i];
            s0 += e[i].x * v0.x + e[i].y * v0.y + e[i].z * v0.z + e[i].w * v0.w;
            s1 += e[i].x * v1.x + e[i].y * v1.y + e[i].z * v1.z + e[i].w * v1.w;
        }
        // two independent shfl chains, interleaved -> latency overlapped
        #pragma unroll
        for (int o = 16; o; o >>= 1) {
            s0 += __shfl_xor_sync(0xFFFFFFFFu, s0, o);
            s1 += __shfl_xor_sync(0xFFFFFFFFu, s1, o);
        }
        if (lane == 0) {
            g_y[(size_t)row * B + b0] = s0;
            if (b1 >= 0) g_y[(size_t)row * B + b1] = s1;
        }
    }
}

// ---------------- scatter: score[b,p] = mean_token y[rank[tok]][b] + c[b] ----------
__global__ void k_scatter(const int* __restrict__ docs,
                          const int* __restrict__ plen,
                          float* __restrict__ out) {
    const int bp = blockIdx.x;           // 512 blocks
    const int b = bp >> 4, p = bp & 15;
    const int t = threadIdx.x;           // 128 threads
    __shared__ int info[2];
    __shared__ float red[128];

    if (t == 0) {
        int start = 0;
        for (int q = 0; q < p; q++) start += plen[b * P + q];
        info[0] = start;
        info[1] = plen[b * P + p];
    }
    __syncthreads();
    const int start = info[0], len = info[1];

    float s = 0.0f;
    for (int tt = t; tt < len; tt += 128) {
        int tok = docs[b * DLEN + start + tt];
        s += g_y[(size_t)g_rank[tok] * B + b];
    }
    red[t] = s;
    __syncthreads();
    for (int o = 64; o; o >>= 1) {
        if (t < o) red[t] += red[t + o];
        __syncthreads();
    }
    if (t == 0) {
        float denom = (float)(len > 0 ? len : 1);
        out[bp] = (len > 0) ? (red[0] / denom + g_c[b]) : 0.0f;
    }
}

// ---------------- launch: 2 streams (3-stream graphs leak upload memory) ------------
extern "C" void kernel_launch(void* const* d_in, const int* in_sizes, int n_in,
                              void* d_out, int out_size) {
    const int*   queries = (const int*)d_in[0];
    const int*   qlen    = (const int*)d_in[1];
    const int*   docs    = (const int*)d_in[2];
    const int*   plen    = (const int*)d_in[3];
    const float* emb     = (const float*)d_in[4];
    const float* W       = (const float*)d_in[5];
    const float* bias    = (const float*)d_in[6];
    float*       out     = (float*)d_out;

    float *qrep_p, *qenc_p, *v_p;
    cudaGetSymbolAddress((void**)&qrep_p, g_qrep);
    cudaGetSymbolAddress((void**)&qenc_p, g_qenc);
    cudaGetSymbolAddress((void**)&v_p, g_v);

    cudaStream_t s2;
    cudaStreamCreateWithFlags(&s2, cudaStreamNonBlocking);
    cudaEvent_t ef, ec, e3, ej;
    cudaEventCreateWithFlags(&ef, cudaEventDisableTiming);
    cudaEventCreateWithFlags(&ec, cudaEventDisableTiming);
    cudaEventCreateWithFlags(&e3, cudaEventDisableTiming);
    cudaEventCreateWithFlags(&ej, cudaEventDisableTiming);

    // dedup pipeline on s2
    cudaEventRecord(ef, 0);
    cudaStreamWaitEvent(s2, ef, 0);
    k_mark<<<B, 256, 0, s2>>>(docs, plen);
    k_compact<<<(V + 255) / 256, 256, 0, s2>>>();
    cudaEventRecord(ec, s2);

    // encode chain on stream 0
    k_qrep<<<dim3(B, 2), 256>>>(queries, qlen, emb);
    k_gemm<<<dim3(32, KSPLIT), 256>>>(qrep_p, W, 0);
    k_reduce<<<128, 128>>>(qenc_p, bias, 1);
    cudaEventRecord(e3, 0);                        // qenc ready
    k_gemm<<<dim3(32, KSPLIT), 256>>>(qenc_p, W, 1);
    k_reduce<<<128, 128>>>(v_p, bias, 0);          // v ready

    // ydot: needs ids+masks (ec) and v (stream 0 order); one warp per full row
    cudaStreamWaitEvent(0, ec, 0);
    k_ydot<<<VPAD / 8, 256>>>(emb);

    // qc off the critical path on s2 (needs qenc)
    cudaStreamWaitEvent(s2, e3, 0);
    k_qc<<<B, 256, 0, s2>>>(bias);
    cudaEventRecord(ej, s2);

    // scatter: needs ydot (stream 0) and qc (ej)
    cudaStreamWaitEvent(0, ej, 0);
    k_scatter<<<B * P, 128>>>(docs, plen, out);
}